// round 8
// baseline (speedup 1.0000x reference)
#include <cuda_runtime.h>
#include <cstdint>

// ============================================================================
// ShiftedWindowAttention — Round 4: conflict-free tf32 mma.sync GEMMs
//   K1: gather(roll+window) + QKV GEMM (tf32) -> g_qkv
//   K2: per (window, head) attention (fp32, vectorized)
//   K3: proj GEMM (tf32) + scatter(window reverse + roll)
//   Layout change vs round 2: smem tiles are [row][BK+4] (stride 68 u32) so
//   fragment LDS banks = gq*4+tq (all distinct) and tile fill is STS.128.
// ============================================================================

#define B_    32
#define HH    56
#define CC    384
#define NH    12
#define DH    32
#define T_    49
#define NWIN  64
#define BN_TOT (B_ * NWIN)       // 2048
#define M_TOT  (BN_TOT * T_)     // 100352

__device__ float g_qkv[(size_t)BN_TOT * 3 * NH * T_ * DH];  // [wi][3][head][t][d]
__device__ float g_att[(size_t)M_TOT * CC];                 // [m][c]

// ---------------------------------------------------------------------------
__device__ __forceinline__ uint32_t f2tf32(float f) {
    uint32_t r;
    asm("cvt.rna.tf32.f32 %0, %1;" : "=r"(r) : "f"(f));
    return r;
}
__device__ __forceinline__ void mma_tf32(float c[4],
                                         uint32_t a0, uint32_t a1, uint32_t a2, uint32_t a3,
                                         uint32_t b0, uint32_t b1) {
    asm volatile(
        "mma.sync.aligned.m16n8k8.row.col.f32.tf32.tf32.f32 "
        "{%0,%1,%2,%3}, {%4,%5,%6,%7}, {%8,%9}, {%0,%1,%2,%3};"
        : "+f"(c[0]), "+f"(c[1]), "+f"(c[2]), "+f"(c[3])
        : "r"(a0), "r"(a1), "r"(a2), "r"(a3), "r"(b0), "r"(b1));
}

// GEMM tiling: block 128x128x64, 8 warps (2x4), warp tile 64x32
constexpr int BKg = 64;
constexpr int AST = BKg + 4;            // 68 u32 row stride
constexpr int SMEM_GEMM = 2 * 128 * AST * 4;   // 69632 B

// ---------------------------------------------------------------------------
// shared inner compute: one BK=64 stage (8 k-steps)
// ---------------------------------------------------------------------------
__device__ __forceinline__ void mma_stage(const uint32_t* __restrict__ As,
                                          const uint32_t* __restrict__ Bs,
                                          int wm, int wn, int gq, int tq,
                                          float c[4][4][4]) {
#pragma unroll
    for (int ks = 0; ks < 8; ks++) {
        const int kk = ks * 8;
        uint32_t bf[4][2];
#pragma unroll
        for (int j = 0; j < 4; j++) {
            int ncol = wn + j * 8 + gq;
            bf[j][0] = Bs[ncol * AST + kk + tq];
            bf[j][1] = Bs[ncol * AST + kk + tq + 4];
        }
#pragma unroll
        for (int i = 0; i < 4; i++) {
            int mrow = wm + i * 16 + gq;
            uint32_t a0 = As[mrow * AST + kk + tq];
            uint32_t a1 = As[(mrow + 8) * AST + kk + tq];
            uint32_t a2 = As[mrow * AST + kk + tq + 4];
            uint32_t a3 = As[(mrow + 8) * AST + kk + tq + 4];
#pragma unroll
            for (int j = 0; j < 4; j++)
                mma_tf32(c[i][j], a0, a1, a2, a3, bf[j][0], bf[j][1]);
        }
    }
}

__device__ __forceinline__ uint4 cvt4(float4 v) {
    uint4 p;
    p.x = f2tf32(v.x); p.y = f2tf32(v.y); p.z = f2tf32(v.z); p.w = f2tf32(v.w);
    return p;
}

// ---------------------------------------------------------------------------
// K1: QKV GEMM, A gathered (roll -3,-3 + window partition)
// ---------------------------------------------------------------------------
__global__ __launch_bounds__(256) void qkv_gemm2(
    const float* __restrict__ x,        // [B,56,56,384]
    const float* __restrict__ w,        // [1152, 384]
    const float* __restrict__ bias)     // [1152]
{
    extern __shared__ uint32_t sm[];
    uint32_t* As = sm;                   // [128][68]
    uint32_t* Bs = sm + 128 * AST;       // [128][68]
    __shared__ int rbase[128];

    const int tid  = threadIdx.x;
    const int lane = tid & 31;
    const int warp = tid >> 5;
    const int m0 = blockIdx.y * 128;
    const int n0 = blockIdx.x * 128;
    const int wm = (warp >> 2) * 64;
    const int wn = (warp & 3) * 32;
    const int gq = lane >> 2;
    const int tq = lane & 3;

    if (tid < 128) {
        int m = m0 + tid;
        int wi = m / T_, t = m - wi * T_;
        int b = wi >> 6, wloc = wi & 63;
        int wr = wloc >> 3, wc = wloc & 7;
        int th = t / 7, tw = t - th * 7;
        int si = wr * 7 + th + 3; if (si >= HH) si -= HH;
        int sj = wc * 7 + tw + 3; if (sj >= HH) sj -= HH;
        rbase[tid] = ((b * HH + si) * HH + sj) * CC;
    }
    __syncthreads();

    float c[4][4][4];
#pragma unroll
    for (int i = 0; i < 4; i++)
#pragma unroll
        for (int j = 0; j < 4; j++)
#pragma unroll
            for (int r = 0; r < 4; r++) c[i][j][r] = 0.f;

    for (int k0 = 0; k0 < CC; k0 += BKg) {
#pragma unroll
        for (int it = 0; it < 8; it++) {
            int slot = it * 256 + tid;         // 0..2047
            int mm = slot >> 4, q = slot & 15; // row, float4 column
            float4 va = *(const float4*)(x + rbase[mm] + k0 + q * 4);
            *(uint4*)(As + mm * AST + q * 4) = cvt4(va);
            float4 vb = *(const float4*)(w + (size_t)(n0 + mm) * CC + k0 + q * 4);
            *(uint4*)(Bs + mm * AST + q * 4) = cvt4(vb);
        }
        __syncthreads();
        mma_stage(As, Bs, wm, wn, gq, tq, c);
        __syncthreads();
    }

    // epilogue: +bias, scatter to g_qkv [wi][3][head][t][d]
#pragma unroll
    for (int i = 0; i < 4; i++) {
        int m_lo = m0 + wm + i * 16 + gq;
        int m_hi = m_lo + 8;
        int wi_lo = m_lo / T_, t_lo = m_lo - wi_lo * T_;
        int wi_hi = m_hi / T_, t_hi = m_hi - wi_hi * T_;
#pragma unroll
        for (int j = 0; j < 4; j++) {
#pragma unroll
            for (int e = 0; e < 2; e++) {
                int n = n0 + wn + j * 8 + 2 * tq + e;
                int which = n / CC;
                int rem = n - which * CC;
                int head = rem >> 5, d = rem & 31;
                float bv = bias[n];
                size_t i_lo = ((((size_t)wi_lo * 3 + which) * NH + head) * T_ + t_lo) * DH + d;
                size_t i_hi = ((((size_t)wi_hi * 3 + which) * NH + head) * T_ + t_hi) * DH + d;
                g_qkv[i_lo] = c[i][j][e] + bv;
                g_qkv[i_hi] = c[i][j][e + 2] + bv;
            }
        }
    }
}

// ---------------------------------------------------------------------------
// K3: proj GEMM + scatter (window reverse + roll +3,+3)
// ---------------------------------------------------------------------------
__global__ __launch_bounds__(256) void proj_gemm2(
    const float* __restrict__ w,        // [384, 384]
    const float* __restrict__ bias,     // [384]
    float* __restrict__ out)            // [B,56,56,384]
{
    extern __shared__ uint32_t sm[];
    uint32_t* As = sm;
    uint32_t* Bs = sm + 128 * AST;

    const int tid  = threadIdx.x;
    const int lane = tid & 31;
    const int warp = tid >> 5;
    const int m0 = blockIdx.y * 128;
    const int n0 = blockIdx.x * 128;
    const int wm = (warp >> 2) * 64;
    const int wn = (warp & 3) * 32;
    const int gq = lane >> 2;
    const int tq = lane & 3;

    float c[4][4][4];
#pragma unroll
    for (int i = 0; i < 4; i++)
#pragma unroll
        for (int j = 0; j < 4; j++)
#pragma unroll
            for (int r = 0; r < 4; r++) c[i][j][r] = 0.f;

    for (int k0 = 0; k0 < CC; k0 += BKg) {
#pragma unroll
        for (int it = 0; it < 8; it++) {
            int slot = it * 256 + tid;
            int mm = slot >> 4, q = slot & 15;
            float4 va = *(const float4*)(g_att + (size_t)(m0 + mm) * CC + k0 + q * 4);
            *(uint4*)(As + mm * AST + q * 4) = cvt4(va);
            float4 vb = *(const float4*)(w + (size_t)(n0 + mm) * CC + k0 + q * 4);
            *(uint4*)(Bs + mm * AST + q * 4) = cvt4(vb);
        }
        __syncthreads();
        mma_stage(As, Bs, wm, wn, gq, tq, c);
        __syncthreads();
    }

    // epilogue: +bias, window-reverse + roll(+3,+3) scatter
#pragma unroll
    for (int i = 0; i < 4; i++) {
#pragma unroll
        for (int e = 0; e < 2; e++) {
            int m = m0 + wm + i * 16 + gq + e * 8;
            int wi = m / T_, t = m - wi * T_;
            int b = wi >> 6, wloc = wi & 63;
            int wr = wloc >> 3, wc = wloc & 7;
            int th = t / 7, tw = t - th * 7;
            int oi = wr * 7 + th + 3; if (oi >= HH) oi -= HH;
            int oj = wc * 7 + tw + 3; if (oj >= HH) oj -= HH;
            float* orow = out + ((size_t)(b * HH + oi) * HH + oj) * CC;
#pragma unroll
            for (int j = 0; j < 4; j++) {
                int n = n0 + wn + j * 8 + 2 * tq;
                orow[n]     = c[i][j][e * 2]     + bias[n];
                orow[n + 1] = c[i][j][e * 2 + 1] + bias[n + 1];
            }
        }
    }
}

// ---------------------------------------------------------------------------
// K2: attention per (window, head) — fp32, float4-vectorized QK & PV
// ---------------------------------------------------------------------------
__global__ __launch_bounds__(256) void attn_kernel(
    const float* __restrict__ table)    // [169, 12]
{
    __shared__ float qs[T_ * 36];
    __shared__ float ks[T_ * 36];
    __shared__ float vs[T_ * 36];
    __shared__ float S[T_ * 50];
    __shared__ float biasc[169];
    __shared__ int th_[T_], tw_[T_], reg_[T_];

    const int tid = threadIdx.x;
    const int wh = blockIdx.x;
    const int wi = wh / NH;
    const int head = wh - wi * NH;
    const int wloc = wi & 63;
    const int wr = wloc >> 3, wc = wloc & 7;

    if (tid < T_) {
        int th = tid / 7, tw = tid - th * 7;
        th_[tid] = th; tw_[tid] = tw;
        int i = wr * 7 + th, j = wc * 7 + tw;
        int hr = (i < 49) ? 0 : ((i < 53) ? 1 : 2);
        int wg = (j < 49) ? 0 : ((j < 53) ? 1 : 2);
        reg_[tid] = hr * 3 + wg;
    }
    if (tid < 169) biasc[tid] = table[tid * NH + head];

    const size_t qb = (((size_t)wi * 3 + 0) * NH + head) * (T_ * DH);
    const float* gq = g_qkv + qb;
    const float* gk = gq + (size_t)NH * T_ * DH;
    const float* gv = gk + (size_t)NH * T_ * DH;
    for (int e = tid; e < T_ * DH; e += 256) {
        int t = e >> 5, d = e & 31;
        qs[t * 36 + d] = gq[e] * 0.17677669529663687f;
        ks[t * 36 + d] = gk[e];
        vs[t * 36 + d] = gv[e];
    }
    __syncthreads();

    // S = q k^T + bias + mask
    for (int e = tid; e < T_ * T_; e += 256) {
        int t = e / T_, s = e - t * T_;
        const float4* q4 = (const float4*)(qs + t * 36);
        const float4* k4 = (const float4*)(ks + s * 36);
        float a = 0.f;
#pragma unroll
        for (int i = 0; i < 8; i++) {
            float4 qv = q4[i], kv = k4[i];
            a += qv.x * kv.x + qv.y * kv.y + qv.z * kv.z + qv.w * kv.w;
        }
        int rp = (th_[t] - th_[s] + 6) * 13 + (tw_[t] - tw_[s] + 6);
        a += biasc[rp];
        if (reg_[t] != reg_[s]) a -= 100.0f;
        S[t * 50 + s] = a;
    }
    __syncthreads();

    // softmax: one thread per row (known-correct round-2 form)
    if (tid < T_) {
        float mx = -1e30f;
#pragma unroll 7
        for (int s = 0; s < T_; s++) mx = fmaxf(mx, S[tid * 50 + s]);
        float sum = 0.f;
#pragma unroll 7
        for (int s = 0; s < T_; s++) {
            float e2 = __expf(S[tid * 50 + s] - mx);
            S[tid * 50 + s] = e2;
            sum += e2;
        }
        float inv = 1.f / sum;
#pragma unroll 7
        for (int s = 0; s < T_; s++) S[tid * 50 + s] *= inv;
    }
    __syncthreads();

    // O = P @ V  (float4 over d)
    for (int o = tid; o < T_ * 8; o += 256) {
        int t = o >> 3, d4 = o & 7;
        float4 acc = make_float4(0.f, 0.f, 0.f, 0.f);
#pragma unroll 7
        for (int s = 0; s < T_; s++) {
            float wv = S[t * 50 + s];
            float4 v4 = *(const float4*)(vs + s * 36 + d4 * 4);
            acc.x += wv * v4.x; acc.y += wv * v4.y;
            acc.z += wv * v4.z; acc.w += wv * v4.w;
        }
        *(float4*)(g_att + ((size_t)wi * T_ + t) * CC + head * DH + d4 * 4) = acc;
    }
}

// ---------------------------------------------------------------------------
extern "C" void kernel_launch(void* const* d_in, const int* in_sizes, int n_in,
                              void* d_out, int out_size)
{
    const float* x     = (const float*)d_in[0];
    const float* qkvw  = (const float*)d_in[1];
    const float* qkvb  = (const float*)d_in[2];
    const float* projw = (const float*)d_in[3];
    const float* projb = (const float*)d_in[4];
    const float* table = (const float*)d_in[5];
    float* out = (float*)d_out;

    // unconditional host-side attribute set (deterministic, not captured)
    cudaFuncSetAttribute(qkv_gemm2,
                         cudaFuncAttributeMaxDynamicSharedMemorySize, SMEM_GEMM);
    cudaFuncSetAttribute(proj_gemm2,
                         cudaFuncAttributeMaxDynamicSharedMemorySize, SMEM_GEMM);

    dim3 g1(9, M_TOT / 128);    // 1152/128 = 9
    qkv_gemm2<<<g1, 256, SMEM_GEMM>>>(x, qkvw, qkvb);

    attn_kernel<<<BN_TOT * NH, 256>>>(table);

    dim3 g3(3, M_TOT / 128);    // 384/128 = 3
    proj_gemm2<<<g3, 256, SMEM_GEMM>>>(projw, projb, out);
}

// round 9
// speedup vs baseline: 1.8847x; 1.8847x over previous
#include <cuda_runtime.h>
#include <cstdint>

// ============================================================================
// ShiftedWindowAttention — Round 5: cp.async double-buffered tf32 GEMMs
//   K1: gather(roll+window) + QKV GEMM (tf32, cp.async pipeline) -> g_qkv
//   K2: per (window, head) attention (fp32, vectorized)
//   K3: proj GEMM (tf32, cp.async pipeline) + scatter(reverse + roll)
// Tiles: block 128x128, BK=32, double-buffered raw-fp32 smem ([row][36]),
// cvt.rna.tf32 applied at fragment-register time (same math as round 2).
// ============================================================================

#define B_    32
#define HH    56
#define CC    384
#define NH    12
#define DH    32
#define T_    49
#define NWIN  64
#define BN_TOT (B_ * NWIN)       // 2048
#define M_TOT  (BN_TOT * T_)     // 100352

__device__ float g_qkv[(size_t)BN_TOT * 3 * NH * T_ * DH];  // [wi][3][head][t][d]
__device__ float g_att[(size_t)M_TOT * CC];                 // [m][c]

// ---------------------------------------------------------------------------
__device__ __forceinline__ uint32_t f2tf32(float f) {
    uint32_t r;
    asm("cvt.rna.tf32.f32 %0, %1;" : "=r"(r) : "f"(f));
    return r;
}
__device__ __forceinline__ void mma_tf32(float c[4],
                                         uint32_t a0, uint32_t a1, uint32_t a2, uint32_t a3,
                                         uint32_t b0, uint32_t b1) {
    asm volatile(
        "mma.sync.aligned.m16n8k8.row.col.f32.tf32.tf32.f32 "
        "{%0,%1,%2,%3}, {%4,%5,%6,%7}, {%8,%9}, {%0,%1,%2,%3};"
        : "+f"(c[0]), "+f"(c[1]), "+f"(c[2]), "+f"(c[3])
        : "r"(a0), "r"(a1), "r"(a2), "r"(a3), "r"(b0), "r"(b1));
}
__device__ __forceinline__ uint32_t smem_u32(const void* p) {
    uint32_t a;
    asm("{ .reg .u64 t; cvta.to.shared.u64 t, %1; cvt.u32.u64 %0, t; }" : "=r"(a) : "l"(p));
    return a;
}
__device__ __forceinline__ void cp16(uint32_t s, const void* g) {
    asm volatile("cp.async.cg.shared.global [%0], [%1], 16;" :: "r"(s), "l"(g));
}
__device__ __forceinline__ void cp_commit() {
    asm volatile("cp.async.commit_group;" ::: "memory");
}
template<int N> __device__ __forceinline__ void cp_wait() {
    asm volatile("cp.async.wait_group %0;" :: "n"(N) : "memory");
}

// tiling: block 128x128, BK=32, 8 warps (2x4), warp tile 64x32
constexpr int BK = 32;
constexpr int RS = 36;                         // row stride in floats (144B)
constexpr int TILE_F = 128 * RS;               // 4608 floats per tile
constexpr int STAGE_F = 2 * TILE_F;            // A + B per stage
constexpr int SMEM_GEMM = 2 * STAGE_F * 4;     // 73728 B
constexpr int NST = CC / BK;                   // 12 stages

// ---------------------------------------------------------------------------
// one BK=32 stage of MMAs (fragments cvt'd in registers)
// ---------------------------------------------------------------------------
__device__ __forceinline__ void mma_stage32(const float* __restrict__ As,
                                            const float* __restrict__ Bs,
                                            int wm, int wn, int gq, int tq,
                                            float c[4][4][4]) {
#pragma unroll
    for (int ks = 0; ks < 4; ks++) {
        const int kk = ks * 8;
        uint32_t bf[4][2];
#pragma unroll
        for (int j = 0; j < 4; j++) {
            int ncol = wn + j * 8 + gq;
            bf[j][0] = f2tf32(Bs[ncol * RS + kk + tq]);
            bf[j][1] = f2tf32(Bs[ncol * RS + kk + tq + 4]);
        }
#pragma unroll
        for (int i = 0; i < 4; i++) {
            int mrow = wm + i * 16 + gq;
            uint32_t a0 = f2tf32(As[mrow * RS + kk + tq]);
            uint32_t a1 = f2tf32(As[(mrow + 8) * RS + kk + tq]);
            uint32_t a2 = f2tf32(As[mrow * RS + kk + tq + 4]);
            uint32_t a3 = f2tf32(As[(mrow + 8) * RS + kk + tq + 4]);
#pragma unroll
            for (int j = 0; j < 4; j++)
                mma_tf32(c[i][j], a0, a1, a2, a3, bf[j][0], bf[j][1]);
        }
    }
}

// ---------------------------------------------------------------------------
// K1: QKV GEMM, A gathered (roll -3,-3 + window partition)
// ---------------------------------------------------------------------------
__global__ __launch_bounds__(256) void qkv_gemm3(
    const float* __restrict__ x,        // [B,56,56,384]
    const float* __restrict__ w,        // [1152, 384]
    const float* __restrict__ bias)     // [1152]
{
    extern __shared__ float sm[];
    __shared__ int rbase[128];
    const uint32_t sb = smem_u32(sm);

    const int tid  = threadIdx.x;
    const int lane = tid & 31;
    const int warp = tid >> 5;
    const int m0 = blockIdx.y * 128;
    const int n0 = blockIdx.x * 128;
    const int wm = (warp >> 2) * 64;
    const int wn = (warp & 3) * 32;
    const int gq = lane >> 2;
    const int tq = lane & 3;

    if (tid < 128) {
        int m = m0 + tid;
        int wi = m / T_, t = m - wi * T_;
        int b = wi >> 6, wloc = wi & 63;
        int wr = wloc >> 3, wc = wloc & 7;
        int th = t / 7, tw = t - th * 7;
        int si = wr * 7 + th + 3; if (si >= HH) si -= HH;
        int sj = wc * 7 + tw + 3; if (sj >= HH) sj -= HH;
        rbase[tid] = ((b * HH + si) * HH + sj) * CC;
    }
    __syncthreads();

    float c[4][4][4];
#pragma unroll
    for (int i = 0; i < 4; i++)
#pragma unroll
        for (int j = 0; j < 4; j++)
#pragma unroll
            for (int r = 0; r < 4; r++) c[i][j][r] = 0.f;

    // issue stage 0
    {
        uint32_t a = sb, b = sb + TILE_F * 4;
#pragma unroll
        for (int it = 0; it < 4; it++) {
            int slot = it * 256 + tid;
            int mm = slot >> 3, q = slot & 7;
            cp16(a + (mm * RS + q * 4) * 4, x + rbase[mm] + q * 4);
            cp16(b + (mm * RS + q * 4) * 4, w + (size_t)(n0 + mm) * CC + q * 4);
        }
        cp_commit();
    }

    for (int s = 0; s < NST; s++) {
        if (s + 1 < NST) {
            const int k0 = (s + 1) * BK;
            uint32_t a = sb + ((s + 1) & 1) * STAGE_F * 4;
            uint32_t b = a + TILE_F * 4;
#pragma unroll
            for (int it = 0; it < 4; it++) {
                int slot = it * 256 + tid;
                int mm = slot >> 3, q = slot & 7;
                cp16(a + (mm * RS + q * 4) * 4, x + rbase[mm] + k0 + q * 4);
                cp16(b + (mm * RS + q * 4) * 4, w + (size_t)(n0 + mm) * CC + k0 + q * 4);
            }
            cp_commit();
            cp_wait<1>();
        } else {
            cp_wait<0>();
        }
        __syncthreads();
        const float* As = sm + (s & 1) * STAGE_F;
        const float* Bs = As + TILE_F;
        mma_stage32(As, Bs, wm, wn, gq, tq, c);
        __syncthreads();
    }

    // epilogue: +bias, scatter to g_qkv [wi][3][head][t][d]  (round-2 form)
#pragma unroll
    for (int i = 0; i < 4; i++) {
        int m_lo = m0 + wm + i * 16 + gq;
        int m_hi = m_lo + 8;
        int wi_lo = m_lo / T_, t_lo = m_lo - wi_lo * T_;
        int wi_hi = m_hi / T_, t_hi = m_hi - wi_hi * T_;
#pragma unroll
        for (int j = 0; j < 4; j++) {
#pragma unroll
            for (int e = 0; e < 2; e++) {
                int n = n0 + wn + j * 8 + 2 * tq + e;
                int which = n / CC;
                int rem = n - which * CC;
                int head = rem >> 5, d = rem & 31;
                float bv = bias[n];
                size_t i_lo = ((((size_t)wi_lo * 3 + which) * NH + head) * T_ + t_lo) * DH + d;
                size_t i_hi = ((((size_t)wi_hi * 3 + which) * NH + head) * T_ + t_hi) * DH + d;
                g_qkv[i_lo] = c[i][j][e] + bv;
                g_qkv[i_hi] = c[i][j][e + 2] + bv;
            }
        }
    }
}

// ---------------------------------------------------------------------------
// K3: proj GEMM + scatter (window reverse + roll +3,+3)
// ---------------------------------------------------------------------------
__global__ __launch_bounds__(256) void proj_gemm3(
    const float* __restrict__ w,        // [384, 384]
    const float* __restrict__ bias,     // [384]
    float* __restrict__ out)            // [B,56,56,384]
{
    extern __shared__ float sm[];
    const uint32_t sb = smem_u32(sm);

    const int tid  = threadIdx.x;
    const int lane = tid & 31;
    const int warp = tid >> 5;
    const int m0 = blockIdx.y * 128;
    const int n0 = blockIdx.x * 128;
    const int wm = (warp >> 2) * 64;
    const int wn = (warp & 3) * 32;
    const int gq = lane >> 2;
    const int tq = lane & 3;

    float c[4][4][4];
#pragma unroll
    for (int i = 0; i < 4; i++)
#pragma unroll
        for (int j = 0; j < 4; j++)
#pragma unroll
            for (int r = 0; r < 4; r++) c[i][j][r] = 0.f;

    {
        uint32_t a = sb, b = sb + TILE_F * 4;
#pragma unroll
        for (int it = 0; it < 4; it++) {
            int slot = it * 256 + tid;
            int mm = slot >> 3, q = slot & 7;
            cp16(a + (mm * RS + q * 4) * 4, g_att + (size_t)(m0 + mm) * CC + q * 4);
            cp16(b + (mm * RS + q * 4) * 4, w + (size_t)(n0 + mm) * CC + q * 4);
        }
        cp_commit();
    }

    for (int s = 0; s < NST; s++) {
        if (s + 1 < NST) {
            const int k0 = (s + 1) * BK;
            uint32_t a = sb + ((s + 1) & 1) * STAGE_F * 4;
            uint32_t b = a + TILE_F * 4;
#pragma unroll
            for (int it = 0; it < 4; it++) {
                int slot = it * 256 + tid;
                int mm = slot >> 3, q = slot & 7;
                cp16(a + (mm * RS + q * 4) * 4, g_att + (size_t)(m0 + mm) * CC + k0 + q * 4);
                cp16(b + (mm * RS + q * 4) * 4, w + (size_t)(n0 + mm) * CC + k0 + q * 4);
            }
            cp_commit();
            cp_wait<1>();
        } else {
            cp_wait<0>();
        }
        __syncthreads();
        const float* As = sm + (s & 1) * STAGE_F;
        const float* Bs = As + TILE_F;
        mma_stage32(As, Bs, wm, wn, gq, tq, c);
        __syncthreads();
    }

    // epilogue: +bias, window-reverse + roll(+3,+3) scatter (round-2 form)
#pragma unroll
    for (int i = 0; i < 4; i++) {
#pragma unroll
        for (int e = 0; e < 2; e++) {
            int m = m0 + wm + i * 16 + gq + e * 8;
            int wi = m / T_, t = m - wi * T_;
            int b = wi >> 6, wloc = wi & 63;
            int wr = wloc >> 3, wc = wloc & 7;
            int th = t / 7, tw = t - th * 7;
            int oi = wr * 7 + th + 3; if (oi >= HH) oi -= HH;
            int oj = wc * 7 + tw + 3; if (oj >= HH) oj -= HH;
            float* orow = out + ((size_t)(b * HH + oi) * HH + oj) * CC;
#pragma unroll
            for (int j = 0; j < 4; j++) {
                int n = n0 + wn + j * 8 + 2 * tq;
                orow[n]     = c[i][j][e * 2]     + bias[n];
                orow[n + 1] = c[i][j][e * 2 + 1] + bias[n + 1];
            }
        }
    }
}

// ---------------------------------------------------------------------------
// K2: attention per (window, head) — fp32, float4-vectorized QK & PV
// ---------------------------------------------------------------------------
__global__ __launch_bounds__(256) void attn_kernel(
    const float* __restrict__ table)    // [169, 12]
{
    __shared__ float qs[T_ * 36];
    __shared__ float ks[T_ * 36];
    __shared__ float vs[T_ * 36];
    __shared__ float S[T_ * 50];
    __shared__ float biasc[169];
    __shared__ int th_[T_], tw_[T_], reg_[T_];

    const int tid = threadIdx.x;
    const int wh = blockIdx.x;
    const int wi = wh / NH;
    const int head = wh - wi * NH;
    const int wloc = wi & 63;
    const int wr = wloc >> 3, wc = wloc & 7;

    if (tid < T_) {
        int th = tid / 7, tw = tid - th * 7;
        th_[tid] = th; tw_[tid] = tw;
        int i = wr * 7 + th, j = wc * 7 + tw;
        int hr = (i < 49) ? 0 : ((i < 53) ? 1 : 2);
        int wg = (j < 49) ? 0 : ((j < 53) ? 1 : 2);
        reg_[tid] = hr * 3 + wg;
    }
    if (tid < 169) biasc[tid] = table[tid * NH + head];

    const size_t qb = (((size_t)wi * 3 + 0) * NH + head) * (T_ * DH);
    const float* gq = g_qkv + qb;
    const float* gk = gq + (size_t)NH * T_ * DH;
    const float* gv = gk + (size_t)NH * T_ * DH;
    for (int e = tid; e < T_ * DH; e += 256) {
        int t = e >> 5, d = e & 31;
        qs[t * 36 + d] = gq[e] * 0.17677669529663687f;
        ks[t * 36 + d] = gk[e];
        vs[t * 36 + d] = gv[e];
    }
    __syncthreads();

    for (int e = tid; e < T_ * T_; e += 256) {
        int t = e / T_, s = e - t * T_;
        const float4* q4 = (const float4*)(qs + t * 36);
        const float4* k4 = (const float4*)(ks + s * 36);
        float a = 0.f;
#pragma unroll
        for (int i = 0; i < 8; i++) {
            float4 qv = q4[i], kv = k4[i];
            a += qv.x * kv.x + qv.y * kv.y + qv.z * kv.z + qv.w * kv.w;
        }
        int rp = (th_[t] - th_[s] + 6) * 13 + (tw_[t] - tw_[s] + 6);
        a += biasc[rp];
        if (reg_[t] != reg_[s]) a -= 100.0f;
        S[t * 50 + s] = a;
    }
    __syncthreads();

    if (tid < T_) {
        float mx = -1e30f;
#pragma unroll 7
        for (int s = 0; s < T_; s++) mx = fmaxf(mx, S[tid * 50 + s]);
        float sum = 0.f;
#pragma unroll 7
        for (int s = 0; s < T_; s++) {
            float e2 = __expf(S[tid * 50 + s] - mx);
            S[tid * 50 + s] = e2;
            sum += e2;
        }
        float inv = 1.f / sum;
#pragma unroll 7
        for (int s = 0; s < T_; s++) S[tid * 50 + s] *= inv;
    }
    __syncthreads();

    for (int o = tid; o < T_ * 8; o += 256) {
        int t = o >> 3, d4 = o & 7;
        float4 acc = make_float4(0.f, 0.f, 0.f, 0.f);
#pragma unroll 7
        for (int s = 0; s < T_; s++) {
            float wv = S[t * 50 + s];
            float4 v4 = *(const float4*)(vs + s * 36 + d4 * 4);
            acc.x += wv * v4.x; acc.y += wv * v4.y;
            acc.z += wv * v4.z; acc.w += wv * v4.w;
        }
        *(float4*)(g_att + ((size_t)wi * T_ + t) * CC + head * DH + d4 * 4) = acc;
    }
}

// ---------------------------------------------------------------------------
extern "C" void kernel_launch(void* const* d_in, const int* in_sizes, int n_in,
                              void* d_out, int out_size)
{
    const float* x     = (const float*)d_in[0];
    const float* qkvw  = (const float*)d_in[1];
    const float* qkvb  = (const float*)d_in[2];
    const float* projw = (const float*)d_in[3];
    const float* projb = (const float*)d_in[4];
    const float* table = (const float*)d_in[5];
    float* out = (float*)d_out;

    cudaFuncSetAttribute(qkv_gemm3,
                         cudaFuncAttributeMaxDynamicSharedMemorySize, SMEM_GEMM);
    cudaFuncSetAttribute(proj_gemm3,
                         cudaFuncAttributeMaxDynamicSharedMemorySize, SMEM_GEMM);

    dim3 g1(9, M_TOT / 128);
    qkv_gemm3<<<g1, 256, SMEM_GEMM>>>(x, qkvw, qkvb);

    attn_kernel<<<BN_TOT * NH, 256>>>(table);

    dim3 g3(3, M_TOT / 128);
    proj_gemm3<<<g3, 256, SMEM_GEMM>>>(projw, projb, out);
}

// round 14
// speedup vs baseline: 1.8863x; 1.0008x over previous
#include <cuda_runtime.h>
#include <cstdint>

// ============================================================================
// ShiftedWindowAttention — Round 5: cp.async double-buffered tf32 GEMMs
//   K1: gather(roll+window) + QKV GEMM (tf32, cp.async pipeline) -> g_qkv
//   K2: per (window, head) attention (fp32, vectorized)
//   K3: proj GEMM (tf32, cp.async pipeline) + scatter(reverse + roll)
// Tiles: block 128x128, BK=32, double-buffered raw-fp32 smem ([row][36]),
// cvt.rna.tf32 applied at fragment-register time (same math as round 2).
// ============================================================================

#define B_    32
#define HH    56
#define CC    384
#define NH    12
#define DH    32
#define T_    49
#define NWIN  64
#define BN_TOT (B_ * NWIN)       // 2048
#define M_TOT  (BN_TOT * T_)     // 100352

__device__ float g_qkv[(size_t)BN_TOT * 3 * NH * T_ * DH];  // [wi][3][head][t][d]
__device__ float g_att[(size_t)M_TOT * CC];                 // [m][c]

// ---------------------------------------------------------------------------
__device__ __forceinline__ uint32_t f2tf32(float f) {
    uint32_t r;
    asm("cvt.rna.tf32.f32 %0, %1;" : "=r"(r) : "f"(f));
    return r;
}
__device__ __forceinline__ void mma_tf32(float c[4],
                                         uint32_t a0, uint32_t a1, uint32_t a2, uint32_t a3,
                                         uint32_t b0, uint32_t b1) {
    asm volatile(
        "mma.sync.aligned.m16n8k8.row.col.f32.tf32.tf32.f32 "
        "{%0,%1,%2,%3}, {%4,%5,%6,%7}, {%8,%9}, {%0,%1,%2,%3};"
        : "+f"(c[0]), "+f"(c[1]), "+f"(c[2]), "+f"(c[3])
        : "r"(a0), "r"(a1), "r"(a2), "r"(a3), "r"(b0), "r"(b1));
}
__device__ __forceinline__ uint32_t smem_u32(const void* p) {
    uint32_t a;
    asm("{ .reg .u64 t; cvta.to.shared.u64 t, %1; cvt.u32.u64 %0, t; }" : "=r"(a) : "l"(p));
    return a;
}
__device__ __forceinline__ void cp16(uint32_t s, const void* g) {
    asm volatile("cp.async.cg.shared.global [%0], [%1], 16;" :: "r"(s), "l"(g));
}
__device__ __forceinline__ void cp_commit() {
    asm volatile("cp.async.commit_group;" ::: "memory");
}
template<int N> __device__ __forceinline__ void cp_wait() {
    asm volatile("cp.async.wait_group %0;" :: "n"(N) : "memory");
}

// tiling: block 128x128, BK=32, 8 warps (2x4), warp tile 64x32
constexpr int BK = 32;
constexpr int RS = 36;                         // row stride in floats (144B)
constexpr int TILE_F = 128 * RS;               // 4608 floats per tile
constexpr int STAGE_F = 2 * TILE_F;            // A + B per stage
constexpr int SMEM_GEMM = 2 * STAGE_F * 4;     // 73728 B
constexpr int NST = CC / BK;                   // 12 stages

// ---------------------------------------------------------------------------
// one BK=32 stage of MMAs (fragments cvt'd in registers)
// ---------------------------------------------------------------------------
__device__ __forceinline__ void mma_stage32(const float* __restrict__ As,
                                            const float* __restrict__ Bs,
                                            int wm, int wn, int gq, int tq,
                                            float c[4][4][4]) {
#pragma unroll
    for (int ks = 0; ks < 4; ks++) {
        const int kk = ks * 8;
        uint32_t bf[4][2];
#pragma unroll
        for (int j = 0; j < 4; j++) {
            int ncol = wn + j * 8 + gq;
            bf[j][0] = f2tf32(Bs[ncol * RS + kk + tq]);
            bf[j][1] = f2tf32(Bs[ncol * RS + kk + tq + 4]);
        }
#pragma unroll
        for (int i = 0; i < 4; i++) {
            int mrow = wm + i * 16 + gq;
            uint32_t a0 = f2tf32(As[mrow * RS + kk + tq]);
            uint32_t a1 = f2tf32(As[(mrow + 8) * RS + kk + tq]);
            uint32_t a2 = f2tf32(As[mrow * RS + kk + tq + 4]);
            uint32_t a3 = f2tf32(As[(mrow + 8) * RS + kk + tq + 4]);
#pragma unroll
            for (int j = 0; j < 4; j++)
                mma_tf32(c[i][j], a0, a1, a2, a3, bf[j][0], bf[j][1]);
        }
    }
}

// ---------------------------------------------------------------------------
// K1: QKV GEMM, A gathered (roll -3,-3 + window partition)
// ---------------------------------------------------------------------------
__global__ __launch_bounds__(256) void qkv_gemm3(
    const float* __restrict__ x,        // [B,56,56,384]
    const float* __restrict__ w,        // [1152, 384]
    const float* __restrict__ bias)     // [1152]
{
    extern __shared__ float sm[];
    __shared__ int rbase[128];
    const uint32_t sb = smem_u32(sm);

    const int tid  = threadIdx.x;
    const int lane = tid & 31;
    const int warp = tid >> 5;
    const int m0 = blockIdx.y * 128;
    const int n0 = blockIdx.x * 128;
    const int wm = (warp >> 2) * 64;
    const int wn = (warp & 3) * 32;
    const int gq = lane >> 2;
    const int tq = lane & 3;

    if (tid < 128) {
        int m = m0 + tid;
        int wi = m / T_, t = m - wi * T_;
        int b = wi >> 6, wloc = wi & 63;
        int wr = wloc >> 3, wc = wloc & 7;
        int th = t / 7, tw = t - th * 7;
        int si = wr * 7 + th + 3; if (si >= HH) si -= HH;
        int sj = wc * 7 + tw + 3; if (sj >= HH) sj -= HH;
        rbase[tid] = ((b * HH + si) * HH + sj) * CC;
    }
    __syncthreads();

    float c[4][4][4];
#pragma unroll
    for (int i = 0; i < 4; i++)
#pragma unroll
        for (int j = 0; j < 4; j++)
#pragma unroll
            for (int r = 0; r < 4; r++) c[i][j][r] = 0.f;

    // issue stage 0
    {
        uint32_t a = sb, b = sb + TILE_F * 4;
#pragma unroll
        for (int it = 0; it < 4; it++) {
            int slot = it * 256 + tid;
            int mm = slot >> 3, q = slot & 7;
            cp16(a + (mm * RS + q * 4) * 4, x + rbase[mm] + q * 4);
            cp16(b + (mm * RS + q * 4) * 4, w + (size_t)(n0 + mm) * CC + q * 4);
        }
        cp_commit();
    }

    for (int s = 0; s < NST; s++) {
        if (s + 1 < NST) {
            const int k0 = (s + 1) * BK;
            uint32_t a = sb + ((s + 1) & 1) * STAGE_F * 4;
            uint32_t b = a + TILE_F * 4;
#pragma unroll
            for (int it = 0; it < 4; it++) {
                int slot = it * 256 + tid;
                int mm = slot >> 3, q = slot & 7;
                cp16(a + (mm * RS + q * 4) * 4, x + rbase[mm] + k0 + q * 4);
                cp16(b + (mm * RS + q * 4) * 4, w + (size_t)(n0 + mm) * CC + k0 + q * 4);
            }
            cp_commit();
            cp_wait<1>();
        } else {
            cp_wait<0>();
        }
        __syncthreads();
        const float* As = sm + (s & 1) * STAGE_F;
        const float* Bs = As + TILE_F;
        mma_stage32(As, Bs, wm, wn, gq, tq, c);
        __syncthreads();
    }

    // epilogue: +bias, scatter to g_qkv [wi][3][head][t][d]  (round-2 form)
#pragma unroll
    for (int i = 0; i < 4; i++) {
        int m_lo = m0 + wm + i * 16 + gq;
        int m_hi = m_lo + 8;
        int wi_lo = m_lo / T_, t_lo = m_lo - wi_lo * T_;
        int wi_hi = m_hi / T_, t_hi = m_hi - wi_hi * T_;
#pragma unroll
        for (int j = 0; j < 4; j++) {
#pragma unroll
            for (int e = 0; e < 2; e++) {
                int n = n0 + wn + j * 8 + 2 * tq + e;
                int which = n / CC;
                int rem = n - which * CC;
                int head = rem >> 5, d = rem & 31;
                float bv = bias[n];
                size_t i_lo = ((((size_t)wi_lo * 3 + which) * NH + head) * T_ + t_lo) * DH + d;
                size_t i_hi = ((((size_t)wi_hi * 3 + which) * NH + head) * T_ + t_hi) * DH + d;
                g_qkv[i_lo] = c[i][j][e] + bv;
                g_qkv[i_hi] = c[i][j][e + 2] + bv;
            }
        }
    }
}

// ---------------------------------------------------------------------------
// K3: proj GEMM + scatter (window reverse + roll +3,+3)
// ---------------------------------------------------------------------------
__global__ __launch_bounds__(256) void proj_gemm3(
    const float* __restrict__ w,        // [384, 384]
    const float* __restrict__ bias,     // [384]
    float* __restrict__ out)            // [B,56,56,384]
{
    extern __shared__ float sm[];
    const uint32_t sb = smem_u32(sm);

    const int tid  = threadIdx.x;
    const int lane = tid & 31;
    const int warp = tid >> 5;
    const int m0 = blockIdx.y * 128;
    const int n0 = blockIdx.x * 128;
    const int wm = (warp >> 2) * 64;
    const int wn = (warp & 3) * 32;
    const int gq = lane >> 2;
    const int tq = lane & 3;

    float c[4][4][4];
#pragma unroll
    for (int i = 0; i < 4; i++)
#pragma unroll
        for (int j = 0; j < 4; j++)
#pragma unroll
            for (int r = 0; r < 4; r++) c[i][j][r] = 0.f;

    {
        uint32_t a = sb, b = sb + TILE_F * 4;
#pragma unroll
        for (int it = 0; it < 4; it++) {
            int slot = it * 256 + tid;
            int mm = slot >> 3, q = slot & 7;
            cp16(a + (mm * RS + q * 4) * 4, g_att + (size_t)(m0 + mm) * CC + q * 4);
            cp16(b + (mm * RS + q * 4) * 4, w + (size_t)(n0 + mm) * CC + q * 4);
        }
        cp_commit();
    }

    for (int s = 0; s < NST; s++) {
        if (s + 1 < NST) {
            const int k0 = (s + 1) * BK;
            uint32_t a = sb + ((s + 1) & 1) * STAGE_F * 4;
            uint32_t b = a + TILE_F * 4;
#pragma unroll
            for (int it = 0; it < 4; it++) {
                int slot = it * 256 + tid;
                int mm = slot >> 3, q = slot & 7;
                cp16(a + (mm * RS + q * 4) * 4, g_att + (size_t)(m0 + mm) * CC + k0 + q * 4);
                cp16(b + (mm * RS + q * 4) * 4, w + (size_t)(n0 + mm) * CC + k0 + q * 4);
            }
            cp_commit();
            cp_wait<1>();
        } else {
            cp_wait<0>();
        }
        __syncthreads();
        const float* As = sm + (s & 1) * STAGE_F;
        const float* Bs = As + TILE_F;
        mma_stage32(As, Bs, wm, wn, gq, tq, c);
        __syncthreads();
    }

    // epilogue: +bias, window-reverse + roll(+3,+3) scatter (round-2 form)
#pragma unroll
    for (int i = 0; i < 4; i++) {
#pragma unroll
        for (int e = 0; e < 2; e++) {
            int m = m0 + wm + i * 16 + gq + e * 8;
            int wi = m / T_, t = m - wi * T_;
            int b = wi >> 6, wloc = wi & 63;
            int wr = wloc >> 3, wc = wloc & 7;
            int th = t / 7, tw = t - th * 7;
            int oi = wr * 7 + th + 3; if (oi >= HH) oi -= HH;
            int oj = wc * 7 + tw + 3; if (oj >= HH) oj -= HH;
            float* orow = out + ((size_t)(b * HH + oi) * HH + oj) * CC;
#pragma unroll
            for (int j = 0; j < 4; j++) {
                int n = n0 + wn + j * 8 + 2 * tq;
                orow[n]     = c[i][j][e * 2]     + bias[n];
                orow[n + 1] = c[i][j][e * 2 + 1] + bias[n + 1];
            }
        }
    }
}

// ---------------------------------------------------------------------------
// K2: attention per (window, head) — fp32, float4-vectorized QK & PV
// ---------------------------------------------------------------------------
__global__ __launch_bounds__(256) void attn_kernel(
    const float* __restrict__ table)    // [169, 12]
{
    __shared__ float qs[T_ * 36];
    __shared__ float ks[T_ * 36];
    __shared__ float vs[T_ * 36];
    __shared__ float S[T_ * 50];
    __shared__ float biasc[169];
    __shared__ int th_[T_], tw_[T_], reg_[T_];

    const int tid = threadIdx.x;
    const int wh = blockIdx.x;
    const int wi = wh / NH;
    const int head = wh - wi * NH;
    const int wloc = wi & 63;
    const int wr = wloc >> 3, wc = wloc & 7;

    if (tid < T_) {
        int th = tid / 7, tw = tid - th * 7;
        th_[tid] = th; tw_[tid] = tw;
        int i = wr * 7 + th, j = wc * 7 + tw;
        int hr = (i < 49) ? 0 : ((i < 53) ? 1 : 2);
        int wg = (j < 49) ? 0 : ((j < 53) ? 1 : 2);
        reg_[tid] = hr * 3 + wg;
    }
    if (tid < 169) biasc[tid] = table[tid * NH + head];

    const size_t qb = (((size_t)wi * 3 + 0) * NH + head) * (T_ * DH);
    const float* gq = g_qkv + qb;
    const float* gk = gq + (size_t)NH * T_ * DH;
    const float* gv = gk + (size_t)NH * T_ * DH;
    for (int e = tid; e < T_ * DH; e += 256) {
        int t = e >> 5, d = e & 31;
        qs[t * 36 + d] = gq[e] * 0.17677669529663687f;
        ks[t * 36 + d] = gk[e];
        vs[t * 36 + d] = gv[e];
    }
    __syncthreads();

    for (int e = tid; e < T_ * T_; e += 256) {
        int t = e / T_, s = e - t * T_;
        const float4* q4 = (const float4*)(qs + t * 36);
        const float4* k4 = (const float4*)(ks + s * 36);
        float a = 0.f;
#pragma unroll
        for (int i = 0; i < 8; i++) {
            float4 qv = q4[i], kv = k4[i];
            a += qv.x * kv.x + qv.y * kv.y + qv.z * kv.z + qv.w * kv.w;
        }
        int rp = (th_[t] - th_[s] + 6) * 13 + (tw_[t] - tw_[s] + 6);
        a += biasc[rp];
        if (reg_[t] != reg_[s]) a -= 100.0f;
        S[t * 50 + s] = a;
    }
    __syncthreads();

    if (tid < T_) {
        float mx = -1e30f;
#pragma unroll 7
        for (int s = 0; s < T_; s++) mx = fmaxf(mx, S[tid * 50 + s]);
        float sum = 0.f;
#pragma unroll 7
        for (int s = 0; s < T_; s++) {
            float e2 = __expf(S[tid * 50 + s] - mx);
            S[tid * 50 + s] = e2;
            sum += e2;
        }
        float inv = 1.f / sum;
#pragma unroll 7
        for (int s = 0; s < T_; s++) S[tid * 50 + s] *= inv;
    }
    __syncthreads();

    for (int o = tid; o < T_ * 8; o += 256) {
        int t = o >> 3, d4 = o & 7;
        float4 acc = make_float4(0.f, 0.f, 0.f, 0.f);
#pragma unroll 7
        for (int s = 0; s < T_; s++) {
            float wv = S[t * 50 + s];
            float4 v4 = *(const float4*)(vs + s * 36 + d4 * 4);
            acc.x += wv * v4.x; acc.y += wv * v4.y;
            acc.z += wv * v4.z; acc.w += wv * v4.w;
        }
        *(float4*)(g_att + ((size_t)wi * T_ + t) * CC + head * DH + d4 * 4) = acc;
    }
}

// ---------------------------------------------------------------------------
extern "C" void kernel_launch(void* const* d_in, const int* in_sizes, int n_in,
                              void* d_out, int out_size)
{
    const float* x     = (const float*)d_in[0];
    const float* qkvw  = (const float*)d_in[1];
    const float* qkvb  = (const float*)d_in[2];
    const float* projw = (const float*)d_in[3];
    const float* projb = (const float*)d_in[4];
    const float* table = (const float*)d_in[5];
    float* out = (float*)d_out;

    cudaFuncSetAttribute(qkv_gemm3,
                         cudaFuncAttributeMaxDynamicSharedMemorySize, SMEM_GEMM);
    cudaFuncSetAttribute(proj_gemm3,
                         cudaFuncAttributeMaxDynamicSharedMemorySize, SMEM_GEMM);

    dim3 g1(9, M_TOT / 128);
    qkv_gemm3<<<g1, 256, SMEM_GEMM>>>(x, qkvw, qkvb);

    attn_kernel<<<BN_TOT * NH, 256>>>(table);

    dim3 g3(3, M_TOT / 128);
    proj_gemm3<<<g3, 256, SMEM_GEMM>>>(projw, projb, out);
}

// round 17
// speedup vs baseline: 1.9593x; 1.0387x over previous
#include <cuda_runtime.h>
#include <cstdint>

// ============================================================================
// ShiftedWindowAttention — Round 6:
//   P:  pre-round x / Wqkv / Wproj to tf32 bit-patterns (removes all in-loop CVT)
//   K1: gather(roll+window) + QKV GEMM (tf32, cp.async double buffer) -> g_qkv
//   K2: attention, register-tiled S (4x4) and PV (4-row x float4); emits
//       tf32-rounded g_att
//   K3: proj GEMM + scatter(window reverse + roll)
// ============================================================================

#define B_    32
#define HH    56
#define CC    384
#define NH    12
#define DH    32
#define T_    49
#define NWIN  64
#define BN_TOT (B_ * NWIN)       // 2048
#define M_TOT  (BN_TOT * T_)     // 100352
#define XN    ((size_t)B_ * HH * HH * CC)

__device__ float g_x32[XN];                                  // tf32-rounded x
__device__ float g_wq32[3 * CC * CC];
__device__ float g_wp32[CC * CC];
__device__ float g_qkv[(size_t)BN_TOT * 3 * NH * T_ * DH];   // [wi][3][head][t][d]
__device__ float g_att[(size_t)M_TOT * CC];                  // [m][c], tf32-rounded

// ---------------------------------------------------------------------------
__device__ __forceinline__ uint32_t f2tf32(float f) {
    uint32_t r;
    asm("cvt.rna.tf32.f32 %0, %1;" : "=r"(r) : "f"(f));
    return r;
}
__device__ __forceinline__ void mma_tf32(float c[4],
                                         uint32_t a0, uint32_t a1, uint32_t a2, uint32_t a3,
                                         uint32_t b0, uint32_t b1) {
    asm volatile(
        "mma.sync.aligned.m16n8k8.row.col.f32.tf32.tf32.f32 "
        "{%0,%1,%2,%3}, {%4,%5,%6,%7}, {%8,%9}, {%0,%1,%2,%3};"
        : "+f"(c[0]), "+f"(c[1]), "+f"(c[2]), "+f"(c[3])
        : "r"(a0), "r"(a1), "r"(a2), "r"(a3), "r"(b0), "r"(b1));
}
__device__ __forceinline__ uint32_t smem_u32(const void* p) {
    uint32_t a;
    asm("{ .reg .u64 t; cvta.to.shared.u64 t, %1; cvt.u32.u64 %0, t; }" : "=r"(a) : "l"(p));
    return a;
}
__device__ __forceinline__ void cp16(uint32_t s, const void* g) {
    asm volatile("cp.async.cg.shared.global [%0], [%1], 16;" :: "r"(s), "l"(g));
}
__device__ __forceinline__ void cp_commit() {
    asm volatile("cp.async.commit_group;" ::: "memory");
}
template<int N> __device__ __forceinline__ void cp_wait() {
    asm volatile("cp.async.wait_group %0;" :: "n"(N) : "memory");
}

// tiling: block 128x128, BK=32, 8 warps (2x4), warp tile 64x32
constexpr int BK = 32;
constexpr int RS = 36;                         // row stride in u32 (144B)
constexpr int TILE_F = 128 * RS;
constexpr int STAGE_F = 2 * TILE_F;
constexpr int SMEM_GEMM = 2 * STAGE_F * 4;     // 73728 B
constexpr int NST = CC / BK;                   // 12

// ---------------------------------------------------------------------------
// pre-round pass
// ---------------------------------------------------------------------------
__global__ void cvt_kernel(const float* __restrict__ src,
                           float* __restrict__ dst, int n4) {
    int i = blockIdx.x * 256 + threadIdx.x;
    if (i >= n4) return;
    float4 v = ((const float4*)src)[i];
    v.x = __uint_as_float(f2tf32(v.x));
    v.y = __uint_as_float(f2tf32(v.y));
    v.z = __uint_as_float(f2tf32(v.z));
    v.w = __uint_as_float(f2tf32(v.w));
    ((float4*)dst)[i] = v;
}

// ---------------------------------------------------------------------------
// one BK=32 stage (no CVT: operands already tf32 bit-patterns)
// ---------------------------------------------------------------------------
__device__ __forceinline__ void mma_stage32(const uint32_t* __restrict__ As,
                                            const uint32_t* __restrict__ Bs,
                                            int wm, int wn, int gq, int tq,
                                            float c[4][4][4]) {
#pragma unroll
    for (int ks = 0; ks < 4; ks++) {
        const int kk = ks * 8;
        uint32_t bf[4][2];
#pragma unroll
        for (int j = 0; j < 4; j++) {
            int ncol = wn + j * 8 + gq;
            bf[j][0] = Bs[ncol * RS + kk + tq];
            bf[j][1] = Bs[ncol * RS + kk + tq + 4];
        }
#pragma unroll
        for (int i = 0; i < 4; i++) {
            int mrow = wm + i * 16 + gq;
            uint32_t a0 = As[mrow * RS + kk + tq];
            uint32_t a1 = As[(mrow + 8) * RS + kk + tq];
            uint32_t a2 = As[mrow * RS + kk + tq + 4];
            uint32_t a3 = As[(mrow + 8) * RS + kk + tq + 4];
#pragma unroll
            for (int j = 0; j < 4; j++)
                mma_tf32(c[i][j], a0, a1, a2, a3, bf[j][0], bf[j][1]);
        }
    }
}

// ---------------------------------------------------------------------------
// K1: QKV GEMM, A gathered (roll -3,-3 + window partition)
// ---------------------------------------------------------------------------
__global__ __launch_bounds__(256) void qkv_gemm4(const float* __restrict__ bias) {
    extern __shared__ uint32_t sm[];
    __shared__ int rbase[128];
    const uint32_t sb = smem_u32(sm);

    const int tid  = threadIdx.x;
    const int lane = tid & 31;
    const int warp = tid >> 5;
    const int m0 = blockIdx.y * 128;
    const int n0 = blockIdx.x * 128;
    const int wm = (warp >> 2) * 64;
    const int wn = (warp & 3) * 32;
    const int gq = lane >> 2;
    const int tq = lane & 3;

    if (tid < 128) {
        int m = m0 + tid;
        int wi = m / T_, t = m - wi * T_;
        int b = wi >> 6, wloc = wi & 63;
        int wr = wloc >> 3, wc = wloc & 7;
        int th = t / 7, tw = t - th * 7;
        int si = wr * 7 + th + 3; if (si >= HH) si -= HH;
        int sj = wc * 7 + tw + 3; if (sj >= HH) sj -= HH;
        rbase[tid] = ((b * HH + si) * HH + sj) * CC;
    }
    __syncthreads();

    float c[4][4][4];
#pragma unroll
    for (int i = 0; i < 4; i++)
#pragma unroll
        for (int j = 0; j < 4; j++)
#pragma unroll
            for (int r = 0; r < 4; r++) c[i][j][r] = 0.f;

    {
        uint32_t a = sb, b = sb + TILE_F * 4;
#pragma unroll
        for (int it = 0; it < 4; it++) {
            int slot = it * 256 + tid;
            int mm = slot >> 3, q = slot & 7;
            cp16(a + (mm * RS + q * 4) * 4, g_x32 + rbase[mm] + q * 4);
            cp16(b + (mm * RS + q * 4) * 4, g_wq32 + (size_t)(n0 + mm) * CC + q * 4);
        }
        cp_commit();
    }

    for (int s = 0; s < NST; s++) {
        if (s + 1 < NST) {
            const int k0 = (s + 1) * BK;
            uint32_t a = sb + ((s + 1) & 1) * STAGE_F * 4;
            uint32_t b = a + TILE_F * 4;
#pragma unroll
            for (int it = 0; it < 4; it++) {
                int slot = it * 256 + tid;
                int mm = slot >> 3, q = slot & 7;
                cp16(a + (mm * RS + q * 4) * 4, g_x32 + rbase[mm] + k0 + q * 4);
                cp16(b + (mm * RS + q * 4) * 4, g_wq32 + (size_t)(n0 + mm) * CC + k0 + q * 4);
            }
            cp_commit();
            cp_wait<1>();
        } else {
            cp_wait<0>();
        }
        __syncthreads();
        const uint32_t* As = sm + (s & 1) * STAGE_F;
        const uint32_t* Bs = As + TILE_F;
        mma_stage32(As, Bs, wm, wn, gq, tq, c);
        __syncthreads();
    }

    // epilogue: +bias, scatter to g_qkv [wi][3][head][t][d]
#pragma unroll
    for (int i = 0; i < 4; i++) {
        int m_lo = m0 + wm + i * 16 + gq;
        int m_hi = m_lo + 8;
        int wi_lo = m_lo / T_, t_lo = m_lo - wi_lo * T_;
        int wi_hi = m_hi / T_, t_hi = m_hi - wi_hi * T_;
#pragma unroll
        for (int j = 0; j < 4; j++) {
#pragma unroll
            for (int e = 0; e < 2; e++) {
                int n = n0 + wn + j * 8 + 2 * tq + e;
                int which = n / CC;
                int rem = n - which * CC;
                int head = rem >> 5, d = rem & 31;
                float bv = bias[n];
                size_t i_lo = ((((size_t)wi_lo * 3 + which) * NH + head) * T_ + t_lo) * DH + d;
                size_t i_hi = ((((size_t)wi_hi * 3 + which) * NH + head) * T_ + t_hi) * DH + d;
                g_qkv[i_lo] = c[i][j][e] + bv;
                g_qkv[i_hi] = c[i][j][e + 2] + bv;
            }
        }
    }
}

// ---------------------------------------------------------------------------
// K3: proj GEMM + scatter (window reverse + roll +3,+3)
// ---------------------------------------------------------------------------
__global__ __launch_bounds__(256) void proj_gemm4(
    const float* __restrict__ bias,
    float* __restrict__ out)
{
    extern __shared__ uint32_t sm[];
    const uint32_t sb = smem_u32(sm);

    const int tid  = threadIdx.x;
    const int lane = tid & 31;
    const int warp = tid >> 5;
    const int m0 = blockIdx.y * 128;
    const int n0 = blockIdx.x * 128;
    const int wm = (warp >> 2) * 64;
    const int wn = (warp & 3) * 32;
    const int gq = lane >> 2;
    const int tq = lane & 3;

    float c[4][4][4];
#pragma unroll
    for (int i = 0; i < 4; i++)
#pragma unroll
        for (int j = 0; j < 4; j++)
#pragma unroll
            for (int r = 0; r < 4; r++) c[i][j][r] = 0.f;

    {
        uint32_t a = sb, b = sb + TILE_F * 4;
#pragma unroll
        for (int it = 0; it < 4; it++) {
            int slot = it * 256 + tid;
            int mm = slot >> 3, q = slot & 7;
            cp16(a + (mm * RS + q * 4) * 4, g_att + (size_t)(m0 + mm) * CC + q * 4);
            cp16(b + (mm * RS + q * 4) * 4, g_wp32 + (size_t)(n0 + mm) * CC + q * 4);
        }
        cp_commit();
    }

    for (int s = 0; s < NST; s++) {
        if (s + 1 < NST) {
            const int k0 = (s + 1) * BK;
            uint32_t a = sb + ((s + 1) & 1) * STAGE_F * 4;
            uint32_t b = a + TILE_F * 4;
#pragma unroll
            for (int it = 0; it < 4; it++) {
                int slot = it * 256 + tid;
                int mm = slot >> 3, q = slot & 7;
                cp16(a + (mm * RS + q * 4) * 4, g_att + (size_t)(m0 + mm) * CC + k0 + q * 4);
                cp16(b + (mm * RS + q * 4) * 4, g_wp32 + (size_t)(n0 + mm) * CC + k0 + q * 4);
            }
            cp_commit();
            cp_wait<1>();
        } else {
            cp_wait<0>();
        }
        __syncthreads();
        const uint32_t* As = sm + (s & 1) * STAGE_F;
        const uint32_t* Bs = As + TILE_F;
        mma_stage32(As, Bs, wm, wn, gq, tq, c);
        __syncthreads();
    }

#pragma unroll
    for (int i = 0; i < 4; i++) {
#pragma unroll
        for (int e = 0; e < 2; e++) {
            int m = m0 + wm + i * 16 + gq + e * 8;
            int wi = m / T_, t = m - wi * T_;
            int b = wi >> 6, wloc = wi & 63;
            int wr = wloc >> 3, wc = wloc & 7;
            int th = t / 7, tw = t - th * 7;
            int oi = wr * 7 + th + 3; if (oi >= HH) oi -= HH;
            int oj = wc * 7 + tw + 3; if (oj >= HH) oj -= HH;
            float* orow = out + ((size_t)(b * HH + oi) * HH + oj) * CC;
#pragma unroll
            for (int j = 0; j < 4; j++) {
                int n = n0 + wn + j * 8 + 2 * tq;
                orow[n]     = c[i][j][e * 2]     + bias[n];
                orow[n + 1] = c[i][j][e * 2 + 1] + bias[n + 1];
            }
        }
    }
}

// ---------------------------------------------------------------------------
// K2: attention per (window, head) — register-tiled S (4x4) and PV (4-row)
// ---------------------------------------------------------------------------
__global__ __launch_bounds__(256) void attn_kernel2(
    const float* __restrict__ table)    // [169, 12]
{
    __shared__ float qs[T_ * 36];
    __shared__ float ks[T_ * 36];
    __shared__ float vs[T_ * 36];
    __shared__ float S[T_ * 50];
    __shared__ float biasc[169];
    __shared__ int th_[T_], tw_[T_], reg_[T_];

    const int tid = threadIdx.x;
    const int wh = blockIdx.x;
    const int wi = wh / NH;
    const int head = wh - wi * NH;
    const int wloc = wi & 63;
    const int wr = wloc >> 3, wc = wloc & 7;

    if (tid < T_) {
        int th = tid / 7, tw = tid - th * 7;
        th_[tid] = th; tw_[tid] = tw;
        int i = wr * 7 + th, j = wc * 7 + tw;
        int hr = (i < 49) ? 0 : ((i < 53) ? 1 : 2);
        int wg = (j < 49) ? 0 : ((j < 53) ? 1 : 2);
        reg_[tid] = hr * 3 + wg;
    }
    if (tid < 169) biasc[tid] = table[tid * NH + head];

    const size_t qb = (((size_t)wi * 3 + 0) * NH + head) * (T_ * DH);
    const float* gq = g_qkv + qb;
    const float* gk = gq + (size_t)NH * T_ * DH;
    const float* gv = gk + (size_t)NH * T_ * DH;
    for (int e = tid; e < T_ * DH; e += 256) {
        int t = e >> 5, d = e & 31;
        qs[t * 36 + d] = gq[e] * 0.17677669529663687f;
        ks[t * 36 + d] = gk[e];
        vs[t * 36 + d] = gv[e];
    }
    __syncthreads();

    // ---- S = q k^T + bias + mask : 4x4 register tiles (13x13 = 169 tiles) ----
    if (tid < 169) {
        const int tt = (tid / 13) * 4;
        const int ss = (tid % 13) * 4;
        int ti[4], si[4];
#pragma unroll
        for (int i = 0; i < 4; i++) {
            ti[i] = min(tt + i, T_ - 1);
            si[i] = min(ss + i, T_ - 1);
        }
        float acc[4][4];
#pragma unroll
        for (int i = 0; i < 4; i++)
#pragma unroll
            for (int j = 0; j < 4; j++) acc[i][j] = 0.f;

#pragma unroll
        for (int dc = 0; dc < 8; dc++) {
            float4 qv[4], kv[4];
#pragma unroll
            for (int i = 0; i < 4; i++) qv[i] = *(const float4*)(qs + ti[i] * 36 + dc * 4);
#pragma unroll
            for (int j = 0; j < 4; j++) kv[j] = *(const float4*)(ks + si[j] * 36 + dc * 4);
#pragma unroll
            for (int i = 0; i < 4; i++)
#pragma unroll
                for (int j = 0; j < 4; j++)
                    acc[i][j] += qv[i].x * kv[j].x + qv[i].y * kv[j].y
                               + qv[i].z * kv[j].z + qv[i].w * kv[j].w;
        }
#pragma unroll
        for (int i = 0; i < 4; i++) {
            int t = tt + i;
            if (t >= T_) break;
#pragma unroll
            for (int j = 0; j < 4; j++) {
                int s = ss + j;
                if (s >= T_) continue;
                float a = acc[i][j];
                int rp = (th_[t] - th_[s] + 6) * 13 + (tw_[t] - tw_[s] + 6);
                a += biasc[rp];
                if (reg_[t] != reg_[s]) a -= 100.0f;
                S[t * 50 + s] = a;
            }
        }
    }
    __syncthreads();

    // ---- softmax per row ----
    if (tid < T_) {
        float mx = -1e30f;
#pragma unroll 7
        for (int s = 0; s < T_; s++) mx = fmaxf(mx, S[tid * 50 + s]);
        float sum = 0.f;
#pragma unroll 7
        for (int s = 0; s < T_; s++) {
            float e2 = __expf(S[tid * 50 + s] - mx);
            S[tid * 50 + s] = e2;
            sum += e2;
        }
        float inv = 1.f / sum;
#pragma unroll 7
        for (int s = 0; s < T_; s++) S[tid * 50 + s] *= inv;
    }
    __syncthreads();

    // ---- O = P @ V : 4-row x float4 tiles (13*8 = 104 tiles), tf32-rounded ----
    if (tid < 104) {
        const int tt = (tid >> 3) * 4;
        const int d4 = tid & 7;
        int ti[4];
#pragma unroll
        for (int i = 0; i < 4; i++) ti[i] = min(tt + i, T_ - 1);
        float4 acc[4];
#pragma unroll
        for (int i = 0; i < 4; i++) acc[i] = make_float4(0.f, 0.f, 0.f, 0.f);

#pragma unroll 7
        for (int s = 0; s < T_; s++) {
            float4 v4 = *(const float4*)(vs + s * 36 + d4 * 4);
            float w0 = S[ti[0] * 50 + s];
            float w1 = S[ti[1] * 50 + s];
            float w2 = S[ti[2] * 50 + s];
            float w3 = S[ti[3] * 50 + s];
            acc[0].x += w0 * v4.x; acc[0].y += w0 * v4.y; acc[0].z += w0 * v4.z; acc[0].w += w0 * v4.w;
            acc[1].x += w1 * v4.x; acc[1].y += w1 * v4.y; acc[1].z += w1 * v4.z; acc[1].w += w1 * v4.w;
            acc[2].x += w2 * v4.x; acc[2].y += w2 * v4.y; acc[2].z += w2 * v4.z; acc[2].w += w2 * v4.w;
            acc[3].x += w3 * v4.x; acc[3].y += w3 * v4.y; acc[3].z += w3 * v4.z; acc[3].w += w3 * v4.w;
        }
#pragma unroll
        for (int i = 0; i < 4; i++) {
            int t = tt + i;
            if (t >= T_) break;
            float4 r;
            r.x = __uint_as_float(f2tf32(acc[i].x));
            r.y = __uint_as_float(f2tf32(acc[i].y));
            r.z = __uint_as_float(f2tf32(acc[i].z));
            r.w = __uint_as_float(f2tf32(acc[i].w));
            *(float4*)(g_att + ((size_t)wi * T_ + t) * CC + head * DH + d4 * 4) = r;
        }
    }
}

// ---------------------------------------------------------------------------
extern "C" void kernel_launch(void* const* d_in, const int* in_sizes, int n_in,
                              void* d_out, int out_size)
{
    const float* x     = (const float*)d_in[0];
    const float* qkvw  = (const float*)d_in[1];
    const float* qkvb  = (const float*)d_in[2];
    const float* projw = (const float*)d_in[3];
    const float* projb = (const float*)d_in[4];
    const float* table = (const float*)d_in[5];
    float* out = (float*)d_out;

    cudaFuncSetAttribute(qkv_gemm4,
                         cudaFuncAttributeMaxDynamicSharedMemorySize, SMEM_GEMM);
    cudaFuncSetAttribute(proj_gemm4,
                         cudaFuncAttributeMaxDynamicSharedMemorySize, SMEM_GEMM);

    float *x32, *wq32, *wp32;
    cudaGetSymbolAddress((void**)&x32,  g_x32);
    cudaGetSymbolAddress((void**)&wq32, g_wq32);
    cudaGetSymbolAddress((void**)&wp32, g_wp32);

    int n4x = (int)(XN / 4);
    cvt_kernel<<<(n4x + 255) / 256, 256>>>(x, x32, n4x);
    int n4q = 3 * CC * CC / 4;
    cvt_kernel<<<(n4q + 255) / 256, 256>>>(qkvw, wq32, n4q);
    int n4p = CC * CC / 4;
    cvt_kernel<<<(n4p + 255) / 256, 256>>>(projw, wp32, n4p);

    dim3 g1(9, M_TOT / 128);
    qkv_gemm4<<<g1, 256, SMEM_GEMM>>>(qkvb);

    attn_kernel2<<<BN_TOT * NH, 256>>>(table);

    dim3 g3(3, M_TOT / 128);
    proj_gemm4<<<g3, 256, SMEM_GEMM>>>(projb, out);
}